// round 14
// baseline (speedup 1.0000x reference)
#include <cuda_runtime.h>
#include <cstdint>

// Problem constants
#define B_   1024
#define N_   256
#define C_   128
#define H_   4
#define T_   4
#define DH   32
#define INTV 64
#define KN   192   // keys per slice = N - INTV

// Scratch (device globals). q/k/att stored as packed fp16x2 along the
// contraction dim; v stored TRANSPOSED ([d][key2]) packed along keys.
// FRAGMENT-PAIR REMAP: within every 8-word group, word at old offset x sits
// at new offset p8(x) = (x&3)*2 + (x>>2), so the mma fragment pair
// (kc*8+q, kc*8+q+4) is ADJACENT -> one LDS.64/LDG.64 per fragment pair.
__device__ uint32_t g_qh[(size_t)B_*H_*N_*(DH/2)];   // [b][h][n][16w remapped], pre-scaled
__device__ uint32_t g_kh[(size_t)B_*H_*N_*(DH/2)];   // [b][h][n][16w remapped]
__device__ uint32_t g_vt[(size_t)B_*H_*DH*(N_/2)];   // [b][h][d][128w remapped]
__device__ uint32_t g_atth[(size_t)B_*N_*(C_/2)];    // [b*n][64w remapped]
__device__ float    g_bias[T_*H_*INTV*KN];           // [i][h][q][kk]
__device__ uint32_t g_wqkv[64*384];                  // word(k2,c) = {w[2k2][c], w[2k2+1][c]}
__device__ uint32_t g_pwh[64*128];                   // word(k2,c) = {pw[2k2][c], pw[2k2+1][c]}

// ---------------------------------------------------------------------------
// helpers
// ---------------------------------------------------------------------------
__device__ __forceinline__ uint32_t pack2(float lo, float hi) {
    uint32_t u;
    asm("cvt.rn.f16x2.f32 %0, %1, %2;" : "=r"(u) : "f"(hi), "f"(lo));
    return u;
}

__device__ __forceinline__ void mma_f16(float4& d,
                                        uint32_t a0, uint32_t a1, uint32_t a2, uint32_t a3,
                                        uint32_t b0, uint32_t b1) {
    asm volatile(
        "mma.sync.aligned.m16n8k16.row.col.f32.f16.f16.f32 "
        "{%0,%1,%2,%3}, {%4,%5,%6,%7}, {%8,%9}, {%0,%1,%2,%3};"
        : "+f"(d.x), "+f"(d.y), "+f"(d.z), "+f"(d.w)
        : "r"(a0), "r"(a1), "r"(a2), "r"(a3), "r"(b0), "r"(b1));
}

__device__ __forceinline__ void cp_async16(uint32_t smem_addr, const void* gptr) {
    asm volatile("cp.async.cg.shared.global [%0], [%1], 16;"
                 :: "r"(smem_addr), "l"(gptr));
}
#define CP_COMMIT()   asm volatile("cp.async.commit_group;" ::: "memory")
#define CP_WAIT_ALL() asm volatile("cp.async.wait_group 0;" ::: "memory")

// p8 remap: old offset within an 8-word group -> new offset
__device__ __forceinline__ int p8(int off) { return (off & 3)*2 + (off >> 2); }

// ---------------------------------------------------------------------------
// Bias precompute
// ---------------------------------------------------------------------------
__global__ void bias_kernel(const float* __restrict__ rpb,
                            const int* __restrict__ rel) {
    int idx = blockIdx.x * 256 + threadIdx.x;
    if (idx >= T_*H_*INTV*KN) return;
    int kk = idx % KN;
    int q  = (idx / KN) % INTV;
    int h  = (idx / (KN*INTV)) % H_;
    int i  =  idx / (KN*INTV*H_);
    int qg = i*INTV + q;
    int kg = (kk < i*INTV) ? kk : kk + INTV;
    g_bias[idx] = rpb[rel[qg*N_ + kg]*H_ + h];
}

// ---------------------------------------------------------------------------
// Weight pre-pack to fp16x2 (one shot, tiny): pairs along the k (row) dim.
// ---------------------------------------------------------------------------
__global__ void wcvt_kernel(const float* __restrict__ qw,
                            const float* __restrict__ kvw,
                            const float* __restrict__ pw) {
    int idx = blockIdx.x * 256 + threadIdx.x;
    if (idx < 64*384) {
        int k2 = idx / 384, c = idx % 384;
        float lo = (c < 128) ? qw[(2*k2)*128 + c]   : kvw[(2*k2)*256 + (c-128)];
        float hi = (c < 128) ? qw[(2*k2+1)*128 + c] : kvw[(2*k2+1)*256 + (c-128)];
        g_wqkv[idx] = pack2(lo, hi);
    } else {
        int p = idx - 64*384;
        if (p < 64*128) {
            int k2 = p / 128, c = p % 128;
            g_pwh[p] = pack2(pw[(2*k2)*128 + c], pw[(2*k2+1)*128 + c]);
        }
    }
}

// ---------------------------------------------------------------------------
// QKV GEMM (fp16 mma): 256 threads, 128-row M-tile, 6 N-chunks of 64.
// Epilogue stores Q/K/att-side layouts with the p8 fragment-pair remap.
// ---------------------------------------------------------------------------
#define QA_LD 68    // A row stride in words (64 + 4 pad)
#define QB_LD 72    // B row stride in words
#define QKV_SMEM_WORDS (128*QA_LD + 64*QB_LD)   // 13312 -> 53,248 B

__global__ __launch_bounds__(256, 2) void qkv_gemm_tc(const float* __restrict__ x) {
    extern __shared__ uint32_t sm[];
    uint32_t* As = sm;                   // [128][QA_LD] packed fp16x2 along k
    uint32_t* Bs = sm + 128*QA_LD;       // [64][QB_LD]  word(k2, c)
    uint32_t BsAddr = (uint32_t)__cvta_generic_to_shared(Bs);

    int tid   = threadIdx.x;
    int mBase = blockIdx.x * 128;

#pragma unroll
    for (int it = 0; it < 16; ++it) {    // A: 128x128 fp32 -> fp16x2
        int idx = tid + it*256;
        int r = idx >> 5, c4 = idx & 31;
        float4 v = *(const float4*)(x + (size_t)(mBase + r)*128 + c4*4);
        uint2 w = make_uint2(pack2(v.x, v.y), pack2(v.z, v.w));
        *(uint2*)&As[r*QA_LD + c4*2] = w;
    }

    int warp = tid >> 5, lane = tid & 31;
    int g = lane >> 2, q = lane & 3;
    int wm = (warp & 3) * 32;
    int wn = (warp >> 2) * 32;

    const float scale = 0.17677669529663687f;  // 32^-0.5 (folded into Q)

#pragma unroll 1
    for (int c = 0; c < 6; ++c) {
        __syncthreads();
#pragma unroll
        for (int it = 0; it < 4; ++it) { // B chunk: 64 k2-rows x 64 cols
            int idx = tid + it*256;
            int r = idx >> 4, c4 = idx & 15;
            cp_async16(BsAddr + (r*QB_LD + c4*4)*4, g_wqkv + r*384 + c*64 + c4*4);
        }
        CP_COMMIT();
        CP_WAIT_ALL();
        __syncthreads();

        float4 acc[2][4];
#pragma unroll
        for (int mi = 0; mi < 2; ++mi)
#pragma unroll
            for (int nj = 0; nj < 4; ++nj) acc[mi][nj] = make_float4(0.f,0.f,0.f,0.f);

#pragma unroll
        for (int kc = 0; kc < 8; ++kc) {  // 8 k16 steps
            uint32_t a[2][4];
#pragma unroll
            for (int mi = 0; mi < 2; ++mi) {
                int r = wm + mi*16 + g;
                a[mi][0] = As[r*QA_LD + kc*8 + q];
                a[mi][1] = As[(r+8)*QA_LD + kc*8 + q];
                a[mi][2] = As[r*QA_LD + kc*8 + q + 4];
                a[mi][3] = As[(r+8)*QA_LD + kc*8 + q + 4];
            }
#pragma unroll
            for (int nj = 0; nj < 4; ++nj) {
                uint32_t b0 = Bs[(kc*8+q)*QB_LD   + wn + nj*8 + g];
                uint32_t b1 = Bs[(kc*8+q+4)*QB_LD + wn + nj*8 + g];
#pragma unroll
                for (int mi = 0; mi < 2; ++mi)
                    mma_f16(acc[mi][nj], a[mi][0], a[mi][1], a[mi][2], a[mi][3], b0, b1);
            }
        }

        // epilogue: cg even pair (cg, cg+1)
        bool isQ = (c < 2);
        bool isV = (c >= 4);
#pragma unroll
        for (int nj = 0; nj < 4; ++nj) {
            int cg = c*64 + wn + nj*8 + 2*q;
#pragma unroll
            for (int mi = 0; mi < 2; ++mi) {
                int r = mBase + wm + mi*16 + g;
                int b = r >> 8, n = r & 255;
                float4 a4 = acc[mi][nj];
                if (!isV) {
                    int cc = isQ ? cg : (cg - 128);
                    int h = cc >> 5, d = cc & 31;
                    int d2o = d >> 1;
                    int d2n = (d2o & ~7) + p8(d2o & 7);   // fragment-pair remap
                    float s = isQ ? scale : 1.0f;
                    size_t w0 = (((size_t)b*H_ + h)*N_ + n)*(DH/2) + d2n;
                    size_t w1 = (((size_t)b*H_ + h)*N_ + (n+8))*(DH/2) + d2n;
                    uint32_t* dst = isQ ? g_qh : g_kh;
                    dst[w0] = pack2(a4.x*s, a4.y*s);
                    dst[w1] = pack2(a4.z*s, a4.w*s);
                } else {
                    // V transposed + remapped: old n2a (off=g/2) and n2b (off=g/2+4)
                    // land adjacent -> single uint2 store per dim.
                    int cc = cg - 256;
                    int h = cc >> 5, d = cc & 31;
                    float px = __shfl_xor_sync(0xffffffffu, a4.x, 4);
                    float py = __shfl_xor_sync(0xffffffffu, a4.y, 4);
                    float pz = __shfl_xor_sync(0xffffffffu, a4.z, 4);
                    float pw = __shfl_xor_sync(0xffffffffu, a4.w, 4);
                    if ((g & 1) == 0) {
                        size_t vb = (((size_t)b*H_ + h)*DH) * (N_/2);
                        int grp = ((n >> 1) & ~7);          // 8-group base of n2a
                        int no  = (g >> 1) * 2;             // new offset (pair adjacent)
                        *(uint2*)&g_vt[vb + (size_t)d    *(N_/2) + grp + no] =
                            make_uint2(pack2(a4.x, px), pack2(a4.z, pz));
                        *(uint2*)&g_vt[vb + (size_t)(d+1)*(N_/2) + grp + no] =
                            make_uint2(pack2(a4.y, py), pack2(a4.w, pw));
                    }
                }
            }
        }
    }
}

// ---------------------------------------------------------------------------
// Projection GEMM (fp16 mma): A = g_atth (remapped words -> LDS.64 frag
// loads), B = g_pwh. out = att @ pw + pb (fp32).
// ---------------------------------------------------------------------------
#define PA_LD 72    // proj A row stride (72%32==8 -> conflict-free LDS.64)
#define PROJ_SMEM_WORDS (128*PA_LD + 64*QB_LD)   // 13824 -> 55,296 B

__global__ __launch_bounds__(256, 2) void proj_gemm_tc(const float* __restrict__ pb,
                                                       float* __restrict__ out) {
    extern __shared__ uint32_t sm[];
    uint32_t* As = sm;                   // [128][PA_LD]
    uint32_t* Bs = sm + 128*PA_LD;       // [64][QB_LD]
    uint32_t AsAddr = (uint32_t)__cvta_generic_to_shared(As);
    uint32_t BsAddr = (uint32_t)__cvta_generic_to_shared(Bs);

    int tid   = threadIdx.x;
    int mBase = blockIdx.x * 128;

#pragma unroll
    for (int it = 0; it < 8; ++it) {     // A: 128 rows x 64 words (remapped)
        int idx = tid + it*256;
        int r = idx >> 4, c4 = idx & 15;
        cp_async16(AsAddr + (r*PA_LD + c4*4)*4,
                   g_atth + (size_t)(mBase + r)*(C_/2) + c4*4);
    }
    CP_COMMIT();

    int warp = tid >> 5, lane = tid & 31;
    int g = lane >> 2, q = lane & 3;
    int wm = (warp & 3) * 32;
    int wn = (warp >> 2) * 32;

#pragma unroll 1
    for (int c = 0; c < 2; ++c) {
        __syncthreads();
#pragma unroll
        for (int it = 0; it < 4; ++it) { // B chunk: 64 k2-rows x 64 cols
            int idx = tid + it*256;
            int r = idx >> 4, c4 = idx & 15;
            cp_async16(BsAddr + (r*QB_LD + c4*4)*4, g_pwh + r*128 + c*64 + c4*4);
        }
        CP_COMMIT();
        CP_WAIT_ALL();
        __syncthreads();

        float4 acc[2][4];
#pragma unroll
        for (int mi = 0; mi < 2; ++mi)
#pragma unroll
            for (int nj = 0; nj < 4; ++nj) acc[mi][nj] = make_float4(0.f,0.f,0.f,0.f);

#pragma unroll
        for (int kc = 0; kc < 8; ++kc) {
            uint32_t a[2][4];
#pragma unroll
            for (int mi = 0; mi < 2; ++mi) {
                int r = wm + mi*16 + g;
                uint2 av0 = *(const uint2*)&As[r*PA_LD + kc*8 + 2*q];
                uint2 av1 = *(const uint2*)&As[(r+8)*PA_LD + kc*8 + 2*q];
                a[mi][0] = av0.x; a[mi][2] = av0.y;
                a[mi][1] = av1.x; a[mi][3] = av1.y;
            }
#pragma unroll
            for (int nj = 0; nj < 4; ++nj) {
                uint32_t b0 = Bs[(kc*8+q)*QB_LD   + wn + nj*8 + g];
                uint32_t b1 = Bs[(kc*8+q+4)*QB_LD + wn + nj*8 + g];
#pragma unroll
                for (int mi = 0; mi < 2; ++mi)
                    mma_f16(acc[mi][nj], a[mi][0], a[mi][1], a[mi][2], a[mi][3], b0, b1);
            }
        }

#pragma unroll
        for (int nj = 0; nj < 4; ++nj) {
            int cg = c*64 + wn + nj*8 + 2*q;
            float2 bias = *(const float2*)(pb + cg);
#pragma unroll
            for (int mi = 0; mi < 2; ++mi) {
                int r = mBase + wm + mi*16 + g;
                float2 v0 = make_float2(acc[mi][nj].x + bias.x, acc[mi][nj].y + bias.y);
                float2 v1 = make_float2(acc[mi][nj].z + bias.x, acc[mi][nj].w + bias.y);
                *(float2*)&out[(size_t)r*C_ + cg]     = v0;
                *(float2*)&out[(size_t)(r+8)*C_ + cg] = v1;
            }
        }
    }
}

// ---------------------------------------------------------------------------
// Attention (fp16 mma): block per (b, h, half). All fragment loads are
// LDS.64/LDG.64 thanks to the p8 remap. QK C-frags feed PV A-frags by fp16x2
// packing (no shuffles). No max-subtraction. Output remapped to g_atth.
// ---------------------------------------------------------------------------
#define KS_LD 24    // 16 words + 8 pad (24%32==24 -> conflict-free LDS.64)
#define VS_LD 136   // 128 words + 8 pad
#define ATTN_SMEM_WORDS (256*KS_LD + 32*VS_LD)   // 10496 -> 41,984 B

__global__ __launch_bounds__(256, 2) void attn_tc() {
    extern __shared__ uint32_t sm[];
    uint32_t* Ks = sm;                   // [256][KS_LD]
    uint32_t* Vs = sm + 256*KS_LD;       // [32][VS_LD]
    uint32_t KsAddr = (uint32_t)__cvta_generic_to_shared(Ks);
    uint32_t VsAddr = (uint32_t)__cvta_generic_to_shared(Vs);

    int tid = threadIdx.x;
    int bid = blockIdx.x;
    int hb = bid & 1;
    int h  = (bid >> 1) & 3;
    int b  = bid >> 3;
    size_t base16 = (((size_t)b*H_ + h) * N_) * (DH/2);
    size_t baseV  = (((size_t)b*H_ + h) * DH) * (N_/2);

#pragma unroll
    for (int it = 0; it < 4; ++it) {     // K: 256 keys x 16 words
        int idx = tid + it*256;
        int r = idx >> 2, c4 = idx & 3;
        cp_async16(KsAddr + (r*KS_LD + c4*4)*4, g_kh + base16 + (size_t)r*16 + c4*4);
    }
#pragma unroll
    for (int it = 0; it < 4; ++it) {     // V: 32 dims x 128 words
        int idx = tid + it*256;
        int d = idx >> 5, c32 = idx & 31;
        cp_async16(VsAddr + (d*VS_LD + c32*4)*4, g_vt + baseV + (size_t)d*(N_/2) + c32*4);
    }
    CP_COMMIT();

    int warp = tid >> 5, lane = tid & 31;
    int g = lane >> 2, q = lane & 3;
    int rloc = warp * 16;                // 0..112 within half
    int i = hb*2 + (warp >> 2);          // slice
    int r0g = hb*128 + rloc + g;         // global query rows
    int r1g = r0g + 8;

    // Q A-frags: LDG.64 of pre-scaled remapped words (overlaps K/V copies)
    uint32_t qa[2][4];
    {
        const uint32_t* qp0 = g_qh + base16 + (size_t)r0g*16;
        const uint32_t* qp1 = g_qh + base16 + (size_t)r1g*16;
#pragma unroll
        for (int kc = 0; kc < 2; ++kc) {
            uint2 u0 = *(const uint2*)&qp0[kc*8 + 2*q];
            uint2 u1 = *(const uint2*)&qp1[kc*8 + 2*q];
            qa[kc][0] = u0.x; qa[kc][2] = u0.y;
            qa[kc][1] = u1.x; qa[kc][3] = u1.y;
        }
    }
    CP_WAIT_ALL();
    __syncthreads();

    const float* bb = g_bias + ((size_t)((i*H_ + h)*INTV + (rloc & 63)))*KN;

    float s0r = 0.f, s1r = 0.f;
    float4 o[4];
#pragma unroll
    for (int nj = 0; nj < 4; ++nj) o[nj] = make_float4(0.f,0.f,0.f,0.f);

#pragma unroll
    for (int ch = 0; ch < 2; ++ch) {
        int cbase = ch * 96;

        // S frags (16 x 96), bias-initialized
        float4 c[12];
#pragma unroll
        for (int kt = 0; kt < 12; ++kt) {
            int col = cbase + kt*8 + 2*q;
            float2 b0 = *(const float2*)(bb + (size_t)(g)*KN + col);
            float2 b1 = *(const float2*)(bb + (size_t)(g+8)*KN + col);
            c[kt] = make_float4(b0.x, b0.y, b1.x, b1.y);
        }

        // S = (scaled Q) K^T + bias, two k16 steps; K frag = one LDS.64
#pragma unroll
        for (int kc = 0; kc < 2; ++kc) {
#pragma unroll
            for (int kt = 0; kt < 12; ++kt) {
                int col = cbase + kt*8;
                int off = (col >= i*INTV) ? INTV : 0;
                int kg = col + g + off;
                uint2 kv2 = *(const uint2*)&Ks[kg*KS_LD + kc*8 + 2*q];
                mma_f16(c[kt], qa[kc][0], qa[kc][1], qa[kc][2], qa[kc][3], kv2.x, kv2.y);
            }
        }

        // exp (no max shift) + row sums
        float cs0 = 0.f, cs1 = 0.f;
#pragma unroll
        for (int kt = 0; kt < 12; ++kt) {
            c[kt].x = __expf(c[kt].x);
            c[kt].y = __expf(c[kt].y);
            c[kt].z = __expf(c[kt].z);
            c[kt].w = __expf(c[kt].w);
            cs0 += c[kt].x + c[kt].y;
            cs1 += c[kt].z + c[kt].w;
        }
        cs0 += __shfl_xor_sync(0xffffffffu, cs0, 1);
        cs0 += __shfl_xor_sync(0xffffffffu, cs0, 2);
        cs1 += __shfl_xor_sync(0xffffffffu, cs1, 1);
        cs1 += __shfl_xor_sync(0xffffffffu, cs1, 2);
        s0r += cs0;
        s1r += cs1;

        // PV: C-frag -> fp16 A-frag by packing; V frag = one LDS.64
#pragma unroll
        for (int kp = 0; kp < 6; ++kp) {
            uint32_t a0 = pack2(c[2*kp].x,   c[2*kp].y);
            uint32_t a1 = pack2(c[2*kp].z,   c[2*kp].w);
            uint32_t a2 = pack2(c[2*kp+1].x, c[2*kp+1].y);
            uint32_t a3 = pack2(c[2*kp+1].z, c[2*kp+1].w);
            int col = cbase + kp*16;
            int off = (col >= i*INTV) ? INTV : 0;
            int kb2 = (col + off) >> 1;
#pragma unroll
            for (int nj = 0; nj < 4; ++nj) {
                uint2 vv2 = *(const uint2*)&Vs[(nj*8+g)*VS_LD + kb2 + 2*q];
                mma_f16(o[nj], a0, a1, a2, a3, vv2.x, vv2.y);
            }
        }
    }

    float inv0 = 1.f / s0r;
    float inv1 = 1.f / s1r;

    // normalize + pack fp16x2 + write with p8 remap (warp-exclusive rows)
#pragma unroll
    for (int nj = 0; nj < 4; ++nj) {
        int d2 = h*(DH/2) + (nj >> 1)*8 + q*2 + (nj & 1);   // remapped word index
        g_atth[((size_t)b*N_ + r0g)*(C_/2) + d2] = pack2(o[nj].x*inv0, o[nj].y*inv0);
        g_atth[((size_t)b*N_ + r1g)*(C_/2) + d2] = pack2(o[nj].z*inv1, o[nj].w*inv1);
    }
}

// ---------------------------------------------------------------------------
// Launch
// ---------------------------------------------------------------------------
extern "C" void kernel_launch(void* const* d_in, const int* in_sizes, int n_in,
                              void* d_out, int out_size) {
    const float* x      = (const float*)d_in[0];
    const float* q_w    = (const float*)d_in[1];
    const float* kv_w   = (const float*)d_in[2];
    const float* proj_w = (const float*)d_in[3];
    const float* proj_b = (const float*)d_in[4];
    const float* rpb    = (const float*)d_in[5];
    const int*   rel    = (const int*)d_in[6];
    float* out = (float*)d_out;

    const int qkv_smem  = QKV_SMEM_WORDS * 4;    // 53,248 B
    const int proj_smem = PROJ_SMEM_WORDS * 4;   // 55,296 B
    const int attn_smem = ATTN_SMEM_WORDS * 4;   // 41,984 B
    cudaFuncSetAttribute(qkv_gemm_tc,  cudaFuncAttributeMaxDynamicSharedMemorySize, qkv_smem);
    cudaFuncSetAttribute(proj_gemm_tc, cudaFuncAttributeMaxDynamicSharedMemorySize, proj_smem);
    cudaFuncSetAttribute(attn_tc,      cudaFuncAttributeMaxDynamicSharedMemorySize, attn_smem);

    bias_kernel<<<(T_*H_*INTV*KN + 255)/256, 256>>>(rpb, rel);
    wcvt_kernel<<<(64*384 + 64*128 + 255)/256, 256>>>(q_w, kv_w, proj_w);
    qkv_gemm_tc<<<(B_*N_)/128, 256, qkv_smem>>>(x);
    attn_tc<<<B_*H_*2, 256, attn_smem>>>();
    proj_gemm_tc<<<(B_*N_)/128, 256, proj_smem>>>(proj_b, out);
}

// round 15
// speedup vs baseline: 1.0702x; 1.0702x over previous
#include <cuda_runtime.h>
#include <cstdint>

// Problem constants
#define B_   1024
#define N_   256
#define C_   128
#define H_   4
#define T_   4
#define DH   32
#define INTV 64
#define KN   192   // keys per slice = N - INTV

// Scratch (device globals). q/k/att stored as packed fp16x2 along the
// contraction dim; v stored TRANSPOSED ([d][key]) packed along keys so the
// PV B-fragment is a single word. fp16 has the same 10 mantissa bits as
// tf32 and all values here are O(1), so precision matches the tf32 version.
__device__ uint32_t g_qh[(size_t)B_*H_*N_*(DH/2)];   // [b][h][n][d2], pre-scaled
__device__ uint32_t g_kh[(size_t)B_*H_*N_*(DH/2)];   // [b][h][n][d2]
__device__ uint32_t g_vt[(size_t)B_*H_*DH*(N_/2)];   // [b][h][d][n2] = {V[2n2][d],V[2n2+1][d]}
__device__ uint32_t g_atth[(size_t)B_*N_*(C_/2)];    // [b*n][c2]
__device__ float    g_bias[T_*H_*INTV*KN];           // [i][h][q][kk]
__device__ uint32_t g_wqkv[64*384];                  // word(k2,c) = {w[2k2][c], w[2k2+1][c]}
__device__ uint32_t g_pwh[64*128];                   // word(k2,c) = {pw[2k2][c], pw[2k2+1][c]}

// ---------------------------------------------------------------------------
// helpers
// ---------------------------------------------------------------------------
__device__ __forceinline__ uint32_t pack2(float lo, float hi) {
    uint32_t u;
    asm("cvt.rn.f16x2.f32 %0, %1, %2;" : "=r"(u) : "f"(hi), "f"(lo));
    return u;
}

__device__ __forceinline__ void mma_f16(float4& d,
                                        uint32_t a0, uint32_t a1, uint32_t a2, uint32_t a3,
                                        uint32_t b0, uint32_t b1) {
    asm volatile(
        "mma.sync.aligned.m16n8k16.row.col.f32.f16.f16.f32 "
        "{%0,%1,%2,%3}, {%4,%5,%6,%7}, {%8,%9}, {%0,%1,%2,%3};"
        : "+f"(d.x), "+f"(d.y), "+f"(d.z), "+f"(d.w)
        : "r"(a0), "r"(a1), "r"(a2), "r"(a3), "r"(b0), "r"(b1));
}

__device__ __forceinline__ void cp_async16(uint32_t smem_addr, const void* gptr) {
    asm volatile("cp.async.cg.shared.global [%0], [%1], 16;"
                 :: "r"(smem_addr), "l"(gptr));
}
#define CP_COMMIT()   asm volatile("cp.async.commit_group;" ::: "memory")
#define CP_WAIT_ALL() asm volatile("cp.async.wait_group 0;" ::: "memory")

// ---------------------------------------------------------------------------
// Bias precompute
// ---------------------------------------------------------------------------
__global__ void bias_kernel(const float* __restrict__ rpb,
                            const int* __restrict__ rel) {
    int idx = blockIdx.x * 256 + threadIdx.x;
    if (idx >= T_*H_*INTV*KN) return;
    int kk = idx % KN;
    int q  = (idx / KN) % INTV;
    int h  = (idx / (KN*INTV)) % H_;
    int i  =  idx / (KN*INTV*H_);
    int qg = i*INTV + q;
    int kg = (kk < i*INTV) ? kk : kk + INTV;
    g_bias[idx] = rpb[rel[qg*N_ + kg]*H_ + h];
}

// ---------------------------------------------------------------------------
// Weight pre-pack to fp16x2 (one shot, tiny): pairs along the k (row) dim.
// ---------------------------------------------------------------------------
__global__ void wcvt_kernel(const float* __restrict__ qw,
                            const float* __restrict__ kvw,
                            const float* __restrict__ pw) {
    int idx = blockIdx.x * 256 + threadIdx.x;
    if (idx < 64*384) {
        int k2 = idx / 384, c = idx % 384;
        float lo = (c < 128) ? qw[(2*k2)*128 + c]   : kvw[(2*k2)*256 + (c-128)];
        float hi = (c < 128) ? qw[(2*k2+1)*128 + c] : kvw[(2*k2+1)*256 + (c-128)];
        g_wqkv[idx] = pack2(lo, hi);
    } else {
        int p = idx - 64*384;
        if (p < 64*128) {
            int k2 = p / 128, c = p % 128;
            g_pwh[p] = pack2(pw[(2*k2)*128 + c], pw[(2*k2+1)*128 + c]);
        }
    }
}

// ---------------------------------------------------------------------------
// QKV GEMM (fp16 mma): 256 threads, 128-row M-tile, 6 N-chunks of 64.
// smem 53.2 KB, regs capped at 85 -> 3 CTAs/SM (24 warps/SM).
// ---------------------------------------------------------------------------
#define QA_LD 68    // A row stride in words (64 + 4 pad)
#define QB_LD 72    // B row stride in words
#define QKV_SMEM_WORDS (128*QA_LD + 64*QB_LD)   // 13312 -> 53,248 B

__global__ __launch_bounds__(256, 3) void qkv_gemm_tc(const float* __restrict__ x) {
    extern __shared__ uint32_t sm[];
    uint32_t* As = sm;                   // [128][QA_LD] packed fp16x2 along k
    uint32_t* Bs = sm + 128*QA_LD;       // [64][QB_LD]  word(k2, c)
    uint32_t BsAddr = (uint32_t)__cvta_generic_to_shared(Bs);

    int tid   = threadIdx.x;
    int mBase = blockIdx.x * 128;

#pragma unroll
    for (int it = 0; it < 16; ++it) {    // A: 128x128 fp32 -> fp16x2
        int idx = tid + it*256;
        int r = idx >> 5, c4 = idx & 31;
        float4 v = *(const float4*)(x + (size_t)(mBase + r)*128 + c4*4);
        uint2 w = make_uint2(pack2(v.x, v.y), pack2(v.z, v.w));
        *(uint2*)&As[r*QA_LD + c4*2] = w;
    }

    int warp = tid >> 5, lane = tid & 31;
    int g = lane >> 2, q = lane & 3;
    int wm = (warp & 3) * 32;
    int wn = (warp >> 2) * 32;

    const float scale = 0.17677669529663687f;  // 32^-0.5 (folded into Q)

#pragma unroll 1
    for (int c = 0; c < 6; ++c) {
        __syncthreads();
#pragma unroll
        for (int it = 0; it < 4; ++it) { // B chunk: 64 k2-rows x 64 cols
            int idx = tid + it*256;
            int r = idx >> 4, c4 = idx & 15;
            cp_async16(BsAddr + (r*QB_LD + c4*4)*4, g_wqkv + r*384 + c*64 + c4*4);
        }
        CP_COMMIT();
        CP_WAIT_ALL();
        __syncthreads();

        float4 acc[2][4];
#pragma unroll
        for (int mi = 0; mi < 2; ++mi)
#pragma unroll
            for (int nj = 0; nj < 4; ++nj) acc[mi][nj] = make_float4(0.f,0.f,0.f,0.f);

#pragma unroll
        for (int kc = 0; kc < 8; ++kc) {  // 8 k16 steps
            uint32_t a[2][4];
#pragma unroll
            for (int mi = 0; mi < 2; ++mi) {
                int r = wm + mi*16 + g;
                a[mi][0] = As[r*QA_LD + kc*8 + q];
                a[mi][1] = As[(r+8)*QA_LD + kc*8 + q];
                a[mi][2] = As[r*QA_LD + kc*8 + q + 4];
                a[mi][3] = As[(r+8)*QA_LD + kc*8 + q + 4];
            }
#pragma unroll
            for (int nj = 0; nj < 4; ++nj) {
                uint32_t b0 = Bs[(kc*8+q)*QB_LD   + wn + nj*8 + g];
                uint32_t b1 = Bs[(kc*8+q+4)*QB_LD + wn + nj*8 + g];
#pragma unroll
                for (int mi = 0; mi < 2; ++mi)
                    mma_f16(acc[mi][nj], a[mi][0], a[mi][1], a[mi][2], a[mi][3], b0, b1);
            }
        }

        // epilogue: cg even pair (cg, cg+1)
        bool isQ = (c < 2);
        bool isV = (c >= 4);
#pragma unroll
        for (int nj = 0; nj < 4; ++nj) {
            int cg = c*64 + wn + nj*8 + 2*q;
#pragma unroll
            for (int mi = 0; mi < 2; ++mi) {
                int r = mBase + wm + mi*16 + g;
                int b = r >> 8, n = r & 255;
                float4 a4 = acc[mi][nj];
                if (!isV) {
                    int cc = isQ ? cg : (cg - 128);
                    int h = cc >> 5, d = cc & 31;
                    float s = isQ ? scale : 1.0f;
                    size_t w0 = (((size_t)b*H_ + h)*N_ + n)*(DH/2) + (d >> 1);
                    size_t w1 = (((size_t)b*H_ + h)*N_ + (n+8))*(DH/2) + (d >> 1);
                    uint32_t* dst = isQ ? g_qh : g_kh;
                    dst[w0] = pack2(a4.x*s, a4.y*s);
                    dst[w1] = pack2(a4.z*s, a4.w*s);
                } else {
                    // V transposed: word(d, n2) = {V[2n2][d], V[2n2+1][d]}
                    int cc = cg - 256;
                    int h = cc >> 5, d = cc & 31;
                    float px = __shfl_xor_sync(0xffffffffu, a4.x, 4);
                    float py = __shfl_xor_sync(0xffffffffu, a4.y, 4);
                    float pz = __shfl_xor_sync(0xffffffffu, a4.z, 4);
                    float pw = __shfl_xor_sync(0xffffffffu, a4.w, 4);
                    if ((g & 1) == 0) {   // even row of the pair
                        size_t vb = (((size_t)b*H_ + h)*DH) * (N_/2);
                        int n2a = n >> 1, n2b = (n + 8) >> 1;
                        g_vt[vb + (size_t)d    *(N_/2) + n2a] = pack2(a4.x, px);
                        g_vt[vb + (size_t)(d+1)*(N_/2) + n2a] = pack2(a4.y, py);
                        g_vt[vb + (size_t)d    *(N_/2) + n2b] = pack2(a4.z, pz);
                        g_vt[vb + (size_t)(d+1)*(N_/2) + n2b] = pack2(a4.w, pw);
                    }
                }
            }
        }
    }
}

// ---------------------------------------------------------------------------
// Projection GEMM (fp16 mma): A = g_atth (packed), B = g_pwh, both cp.async.
// out = att @ pw + pb (fp32). smem 53.2 KB, regs <=85 -> 3 CTAs/SM.
// ---------------------------------------------------------------------------
__global__ __launch_bounds__(256, 3) void proj_gemm_tc(const float* __restrict__ pb,
                                                       float* __restrict__ out) {
    extern __shared__ uint32_t sm[];
    uint32_t* As = sm;                   // [128][QA_LD]
    uint32_t* Bs = sm + 128*QA_LD;       // [64][QB_LD]
    uint32_t AsAddr = (uint32_t)__cvta_generic_to_shared(As);
    uint32_t BsAddr = (uint32_t)__cvta_generic_to_shared(Bs);

    int tid   = threadIdx.x;
    int mBase = blockIdx.x * 128;

#pragma unroll
    for (int it = 0; it < 8; ++it) {     // A: 128 rows x 64 words
        int idx = tid + it*256;
        int r = idx >> 4, c4 = idx & 15;
        cp_async16(AsAddr + (r*QA_LD + c4*4)*4,
                   g_atth + (size_t)(mBase + r)*(C_/2) + c4*4);
    }
    CP_COMMIT();

    int warp = tid >> 5, lane = tid & 31;
    int g = lane >> 2, q = lane & 3;
    int wm = (warp & 3) * 32;
    int wn = (warp >> 2) * 32;

#pragma unroll 1
    for (int c = 0; c < 2; ++c) {
        __syncthreads();
#pragma unroll
        for (int it = 0; it < 4; ++it) { // B chunk: 64 k2-rows x 64 cols
            int idx = tid + it*256;
            int r = idx >> 4, c4 = idx & 15;
            cp_async16(BsAddr + (r*QB_LD + c4*4)*4, g_pwh + r*128 + c*64 + c4*4);
        }
        CP_COMMIT();
        CP_WAIT_ALL();
        __syncthreads();

        float4 acc[2][4];
#pragma unroll
        for (int mi = 0; mi < 2; ++mi)
#pragma unroll
            for (int nj = 0; nj < 4; ++nj) acc[mi][nj] = make_float4(0.f,0.f,0.f,0.f);

#pragma unroll
        for (int kc = 0; kc < 8; ++kc) {
            uint32_t a[2][4];
#pragma unroll
            for (int mi = 0; mi < 2; ++mi) {
                int r = wm + mi*16 + g;
                a[mi][0] = As[r*QA_LD + kc*8 + q];
                a[mi][1] = As[(r+8)*QA_LD + kc*8 + q];
                a[mi][2] = As[r*QA_LD + kc*8 + q + 4];
                a[mi][3] = As[(r+8)*QA_LD + kc*8 + q + 4];
            }
#pragma unroll
            for (int nj = 0; nj < 4; ++nj) {
                uint32_t b0 = Bs[(kc*8+q)*QB_LD   + wn + nj*8 + g];
                uint32_t b1 = Bs[(kc*8+q+4)*QB_LD + wn + nj*8 + g];
#pragma unroll
                for (int mi = 0; mi < 2; ++mi)
                    mma_f16(acc[mi][nj], a[mi][0], a[mi][1], a[mi][2], a[mi][3], b0, b1);
            }
        }

#pragma unroll
        for (int nj = 0; nj < 4; ++nj) {
            int cg = c*64 + wn + nj*8 + 2*q;
            float2 bias = *(const float2*)(pb + cg);
#pragma unroll
            for (int mi = 0; mi < 2; ++mi) {
                int r = mBase + wm + mi*16 + g;
                float2 v0 = make_float2(acc[mi][nj].x + bias.x, acc[mi][nj].y + bias.y);
                float2 v1 = make_float2(acc[mi][nj].z + bias.x, acc[mi][nj].w + bias.y);
                *(float2*)&out[(size_t)r*C_ + cg]     = v0;
                *(float2*)&out[(size_t)(r+8)*C_ + cg] = v1;
            }
        }
    }
}

// ---------------------------------------------------------------------------
// Attention (fp16 mma): block per (b, h, half) -> 8192 blocks, 256 threads.
// THREE 64-key chunks (8 live S-frags -> fits the 85-reg cap) -> 3 CTAs/SM,
// 24 warps/SM. QK C-frags feed PV A-frags by fp16x2 packing (no shuffles).
// No max-subtraction (logits tiny). Output packed fp16x2 to g_atth.
// ---------------------------------------------------------------------------
#define KS_LD 20    // 16 words + 4 pad
#define VS_LD 132   // 128 words + 4 pad
#define ATTN_SMEM_WORDS (256*KS_LD + 32*VS_LD)   // 9344 -> 37,376 B

__global__ __launch_bounds__(256, 3) void attn_tc() {
    extern __shared__ uint32_t sm[];
    uint32_t* Ks = sm;                   // [256][KS_LD]
    uint32_t* Vs = sm + 256*KS_LD;       // [32][VS_LD]
    uint32_t KsAddr = (uint32_t)__cvta_generic_to_shared(Ks);
    uint32_t VsAddr = (uint32_t)__cvta_generic_to_shared(Vs);

    int tid = threadIdx.x;
    int bid = blockIdx.x;
    int hb = bid & 1;
    int h  = (bid >> 1) & 3;
    int b  = bid >> 3;
    size_t base16 = (((size_t)b*H_ + h) * N_) * (DH/2);
    size_t baseV  = (((size_t)b*H_ + h) * DH) * (N_/2);

#pragma unroll
    for (int it = 0; it < 4; ++it) {     // K: 256 keys x 16 words
        int idx = tid + it*256;
        int r = idx >> 2, c4 = idx & 3;
        cp_async16(KsAddr + (r*KS_LD + c4*4)*4, g_kh + base16 + (size_t)r*16 + c4*4);
    }
#pragma unroll
    for (int it = 0; it < 4; ++it) {     // V: 32 dims x 128 words
        int idx = tid + it*256;
        int d = idx >> 5, c32 = idx & 31;
        cp_async16(VsAddr + (d*VS_LD + c32*4)*4, g_vt + baseV + (size_t)d*(N_/2) + c32*4);
    }
    CP_COMMIT();

    int warp = tid >> 5, lane = tid & 31;
    int g = lane >> 2, q = lane & 3;
    int rloc = warp * 16;                // 0..112 within half
    int i = hb*2 + (warp >> 2);          // slice
    int r0g = hb*128 + rloc + g;         // global query rows
    int r1g = r0g + 8;

    // Q A-frags: direct LDG of pre-scaled packed words (overlaps K/V copies)
    uint32_t qa[2][4];
    {
        const uint32_t* qp0 = g_qh + base16 + (size_t)r0g*16;
        const uint32_t* qp1 = g_qh + base16 + (size_t)r1g*16;
#pragma unroll
        for (int kc = 0; kc < 2; ++kc) {
            qa[kc][0] = qp0[kc*8 + q];
            qa[kc][1] = qp1[kc*8 + q];
            qa[kc][2] = qp0[kc*8 + q + 4];
            qa[kc][3] = qp1[kc*8 + q + 4];
        }
    }
    CP_WAIT_ALL();
    __syncthreads();

    const float* bb = g_bias + ((size_t)((i*H_ + h)*INTV + (rloc & 63)))*KN;

    float s0r = 0.f, s1r = 0.f;
    float4 o[4];
#pragma unroll
    for (int nj = 0; nj < 4; ++nj) o[nj] = make_float4(0.f,0.f,0.f,0.f);

#pragma unroll
    for (int ch = 0; ch < 3; ++ch) {     // 3 chunks of 64 keys
        int cbase = ch * 64;

        // S frags (16 x 64), bias-initialized
        float4 c[8];
#pragma unroll
        for (int kt = 0; kt < 8; ++kt) {
            int col = cbase + kt*8 + 2*q;
            float2 b0 = *(const float2*)(bb + (size_t)(g)*KN + col);
            float2 b1 = *(const float2*)(bb + (size_t)(g+8)*KN + col);
            c[kt] = make_float4(b0.x, b0.y, b1.x, b1.y);
        }

        // S = (scaled Q) K^T + bias, two k16 steps
#pragma unroll
        for (int kc = 0; kc < 2; ++kc) {
#pragma unroll
            for (int kt = 0; kt < 8; ++kt) {
                int col = cbase + kt*8;
                int off = (col >= i*INTV) ? INTV : 0;
                int kg = col + g + off;
                uint32_t b0 = Ks[kg*KS_LD + kc*8 + q];
                uint32_t b1 = Ks[kg*KS_LD + kc*8 + q + 4];
                mma_f16(c[kt], qa[kc][0], qa[kc][1], qa[kc][2], qa[kc][3], b0, b1);
            }
        }

        // exp (no max shift) + row sums
        float cs0 = 0.f, cs1 = 0.f;
#pragma unroll
        for (int kt = 0; kt < 8; ++kt) {
            c[kt].x = __expf(c[kt].x);
            c[kt].y = __expf(c[kt].y);
            c[kt].z = __expf(c[kt].z);
            c[kt].w = __expf(c[kt].w);
            cs0 += c[kt].x + c[kt].y;
            cs1 += c[kt].z + c[kt].w;
        }
        cs0 += __shfl_xor_sync(0xffffffffu, cs0, 1);
        cs0 += __shfl_xor_sync(0xffffffffu, cs0, 2);
        cs1 += __shfl_xor_sync(0xffffffffu, cs1, 1);
        cs1 += __shfl_xor_sync(0xffffffffu, cs1, 2);
        s0r += cs0;
        s1r += cs1;

        // PV: C-frag -> fp16 A-frag by packing (NO shuffles), 4 k16 steps
#pragma unroll
        for (int kp = 0; kp < 4; ++kp) {
            uint32_t a0 = pack2(c[2*kp].x,   c[2*kp].y);
            uint32_t a1 = pack2(c[2*kp].z,   c[2*kp].w);
            uint32_t a2 = pack2(c[2*kp+1].x, c[2*kp+1].y);
            uint32_t a3 = pack2(c[2*kp+1].z, c[2*kp+1].w);
            int col = cbase + kp*16;
            int off = (col >= i*INTV) ? INTV : 0;
            int kb2 = (col + off) >> 1;
#pragma unroll
            for (int nj = 0; nj < 4; ++nj) {
                uint32_t b0 = Vs[(nj*8+g)*VS_LD + kb2 + q];
                uint32_t b1 = Vs[(nj*8+g)*VS_LD + kb2 + q + 4];
                mma_f16(o[nj], a0, a1, a2, a3, b0, b1);
            }
        }
    }

    float inv0 = 1.f / s0r;
    float inv1 = 1.f / s1r;

    // normalize + pack fp16x2 + write (warp-exclusive rows)
#pragma unroll
    for (int nj = 0; nj < 4; ++nj) {
        int d2 = h*(DH/2) + nj*4 + q;   // word index of col pair (2q,2q+1)
        g_atth[((size_t)b*N_ + r0g)*(C_/2) + d2] = pack2(o[nj].x*inv0, o[nj].y*inv0);
        g_atth[((size_t)b*N_ + r1g)*(C_/2) + d2] = pack2(o[nj].z*inv1, o[nj].w*inv1);
    }
}

// ---------------------------------------------------------------------------
// Launch
// ---------------------------------------------------------------------------
extern "C" void kernel_launch(void* const* d_in, const int* in_sizes, int n_in,
                              void* d_out, int out_size) {
    const float* x      = (const float*)d_in[0];
    const float* q_w    = (const float*)d_in[1];
    const float* kv_w   = (const float*)d_in[2];
    const float* proj_w = (const float*)d_in[3];
    const float* proj_b = (const float*)d_in[4];
    const float* rpb    = (const float*)d_in[5];
    const int*   rel    = (const int*)d_in[6];
    float* out = (float*)d_out;

    const int gemm_smem = QKV_SMEM_WORDS * 4;    // 53,248 B -> 3 CTAs/SM
    const int attn_smem = ATTN_SMEM_WORDS * 4;   // 37,376 B -> 3 CTAs/SM
    cudaFuncSetAttribute(qkv_gemm_tc,  cudaFuncAttributeMaxDynamicSharedMemorySize, gemm_smem);
    cudaFuncSetAttribute(proj_gemm_tc, cudaFuncAttributeMaxDynamicSharedMemorySize, gemm_smem);
    cudaFuncSetAttribute(attn_tc,      cudaFuncAttributeMaxDynamicSharedMemorySize, attn_smem);

    bias_kernel<<<(T_*H_*INTV*KN + 255)/256, 256>>>(rpb, rel);
    wcvt_kernel<<<(64*384 + 64*128 + 255)/256, 256>>>(q_w, kv_w, proj_w);
    qkv_gemm_tc<<<(B_*N_)/128, 256, gemm_smem>>>(x);
    attn_tc<<<B_*H_*2, 256, attn_smem>>>();
    proj_gemm_tc<<<(B_*N_)/128, 256, gemm_smem>>>(proj_b, out);
}

// round 16
// speedup vs baseline: 1.0925x; 1.0209x over previous
#include <cuda_runtime.h>
#include <cstdint>

// Problem constants
#define B_   1024
#define N_   256
#define C_   128
#define H_   4
#define T_   4
#define DH   32
#define INTV 64
#define KN   192   // keys per slice = N - INTV

// Scratch (device globals). q/k/att stored as packed fp16x2 along the
// contraction dim; v stored TRANSPOSED ([d][key]) packed along keys so the
// PV B-fragment is a single word. These layouts match ldmatrix.m8n8
// fragment distribution exactly (lane l <- word l%4 of row l/4).
__device__ uint32_t g_qh[(size_t)B_*H_*N_*(DH/2)];   // [b][h][n][d2], pre-scaled
__device__ uint32_t g_kh[(size_t)B_*H_*N_*(DH/2)];   // [b][h][n][d2]
__device__ uint32_t g_vt[(size_t)B_*H_*DH*(N_/2)];   // [b][h][d][n2]
__device__ uint32_t g_atth[(size_t)B_*N_*(C_/2)];    // [b*n][c2]
__device__ float    g_bias[T_*H_*INTV*KN];           // [i][h][q][kk]
__device__ uint32_t g_wqkv[64*384];                  // word(k2,c) = {w[2k2][c], w[2k2+1][c]}
__device__ uint32_t g_pwh[64*128];                   // word(k2,c)

// ---------------------------------------------------------------------------
// helpers
// ---------------------------------------------------------------------------
__device__ __forceinline__ uint32_t pack2(float lo, float hi) {
    uint32_t u;
    asm("cvt.rn.f16x2.f32 %0, %1, %2;" : "=r"(u) : "f"(hi), "f"(lo));
    return u;
}

__device__ __forceinline__ void mma_f16(float4& d,
                                        uint32_t a0, uint32_t a1, uint32_t a2, uint32_t a3,
                                        uint32_t b0, uint32_t b1) {
    asm volatile(
        "mma.sync.aligned.m16n8k16.row.col.f32.f16.f16.f32 "
        "{%0,%1,%2,%3}, {%4,%5,%6,%7}, {%8,%9}, {%0,%1,%2,%3};"
        : "+f"(d.x), "+f"(d.y), "+f"(d.z), "+f"(d.w)
        : "r"(a0), "r"(a1), "r"(a2), "r"(a3), "r"(b0), "r"(b1));
}

__device__ __forceinline__ void ldsm_x4(uint32_t& r0, uint32_t& r1,
                                        uint32_t& r2, uint32_t& r3, uint32_t addr) {
    asm volatile("ldmatrix.sync.aligned.m8n8.x4.shared.b16 {%0,%1,%2,%3}, [%4];"
                 : "=r"(r0), "=r"(r1), "=r"(r2), "=r"(r3) : "r"(addr));
}

__device__ __forceinline__ void cp_async16(uint32_t smem_addr, const void* gptr) {
    asm volatile("cp.async.cg.shared.global [%0], [%1], 16;"
                 :: "r"(smem_addr), "l"(gptr));
}
#define CP_COMMIT()   asm volatile("cp.async.commit_group;" ::: "memory")
#define CP_WAIT_ALL() asm volatile("cp.async.wait_group 0;" ::: "memory")

// ---------------------------------------------------------------------------
// Bias precompute
// ---------------------------------------------------------------------------
__global__ void bias_kernel(const float* __restrict__ rpb,
                            const int* __restrict__ rel) {
    int idx = blockIdx.x * 256 + threadIdx.x;
    if (idx >= T_*H_*INTV*KN) return;
    int kk = idx % KN;
    int q  = (idx / KN) % INTV;
    int h  = (idx / (KN*INTV)) % H_;
    int i  =  idx / (KN*INTV*H_);
    int qg = i*INTV + q;
    int kg = (kk < i*INTV) ? kk : kk + INTV;
    g_bias[idx] = rpb[rel[qg*N_ + kg]*H_ + h];
}

// ---------------------------------------------------------------------------
// Weight pre-pack to fp16x2 (one shot, tiny): pairs along the k (row) dim.
// ---------------------------------------------------------------------------
__global__ void wcvt_kernel(const float* __restrict__ qw,
                            const float* __restrict__ kvw,
                            const float* __restrict__ pw) {
    int idx = blockIdx.x * 256 + threadIdx.x;
    if (idx < 64*384) {
        int k2 = idx / 384, c = idx % 384;
        float lo = (c < 128) ? qw[(2*k2)*128 + c]   : kvw[(2*k2)*256 + (c-128)];
        float hi = (c < 128) ? qw[(2*k2+1)*128 + c] : kvw[(2*k2+1)*256 + (c-128)];
        g_wqkv[idx] = pack2(lo, hi);
    } else {
        int p = idx - 64*384;
        if (p < 64*128) {
            int k2 = p / 128, c = p % 128;
            g_pwh[p] = pack2(pw[(2*k2)*128 + c], pw[(2*k2+1)*128 + c]);
        }
    }
}

// ---------------------------------------------------------------------------
// QKV GEMM (fp16 mma): 256 threads, 128-row M-tile, 6 N-chunks of 64.
// A-frags via ldmatrix.x4. smem 53.2 KB, regs<=85 -> 3 CTAs/SM.
// ---------------------------------------------------------------------------
#define QA_LD 68    // A row stride in words (68%32==4 -> LDSM conflict-free)
#define QB_LD 72    // B row stride in words
#define QKV_SMEM_WORDS (128*QA_LD + 64*QB_LD)   // 13312 -> 53,248 B

__global__ __launch_bounds__(256, 3) void qkv_gemm_tc(const float* __restrict__ x) {
    extern __shared__ uint32_t sm[];
    uint32_t* As = sm;                   // [128][QA_LD] packed fp16x2 along k
    uint32_t* Bs = sm + 128*QA_LD;       // [64][QB_LD]  word(k2, c)
    uint32_t AsAddr = (uint32_t)__cvta_generic_to_shared(As);
    uint32_t BsAddr = (uint32_t)__cvta_generic_to_shared(Bs);

    int tid   = threadIdx.x;
    int mBase = blockIdx.x * 128;

#pragma unroll
    for (int it = 0; it < 16; ++it) {    // A: 128x128 fp32 -> fp16x2
        int idx = tid + it*256;
        int r = idx >> 5, c4 = idx & 31;
        float4 v = *(const float4*)(x + (size_t)(mBase + r)*128 + c4*4);
        uint2 w = make_uint2(pack2(v.x, v.y), pack2(v.z, v.w));
        *(uint2*)&As[r*QA_LD + c4*2] = w;
    }

    int warp = tid >> 5, lane = tid & 31;
    int g = lane >> 2, q = lane & 3;
    int lm = lane >> 3, lr = lane & 7;   // ldmatrix: matrix id, row id
    int wm = (warp & 3) * 32;
    int wn = (warp >> 2) * 32;

    const float scale = 0.17677669529663687f;  // 32^-0.5 (folded into Q)

#pragma unroll 1
    for (int c = 0; c < 6; ++c) {
        __syncthreads();
#pragma unroll
        for (int it = 0; it < 4; ++it) { // B chunk: 64 k2-rows x 64 cols
            int idx = tid + it*256;
            int r = idx >> 4, c4 = idx & 15;
            cp_async16(BsAddr + (r*QB_LD + c4*4)*4, g_wqkv + r*384 + c*64 + c4*4);
        }
        CP_COMMIT();
        CP_WAIT_ALL();
        __syncthreads();

        float4 acc[2][4];
#pragma unroll
        for (int mi = 0; mi < 2; ++mi)
#pragma unroll
            for (int nj = 0; nj < 4; ++nj) acc[mi][nj] = make_float4(0.f,0.f,0.f,0.f);

#pragma unroll
        for (int kc = 0; kc < 8; ++kc) {  // 8 k16 steps
            uint32_t a[2][4];
#pragma unroll
            for (int mi = 0; mi < 2; ++mi) {
                uint32_t addr = AsAddr +
                    (((wm + mi*16 + (lm & 1)*8 + lr)*QA_LD) + kc*8 + (lm >> 1)*4)*4;
                ldsm_x4(a[mi][0], a[mi][1], a[mi][2], a[mi][3], addr);
            }
#pragma unroll
            for (int nj = 0; nj < 4; ++nj) {
                uint32_t b0 = Bs[(kc*8+q)*QB_LD   + wn + nj*8 + g];
                uint32_t b1 = Bs[(kc*8+q+4)*QB_LD + wn + nj*8 + g];
#pragma unroll
                for (int mi = 0; mi < 2; ++mi)
                    mma_f16(acc[mi][nj], a[mi][0], a[mi][1], a[mi][2], a[mi][3], b0, b1);
            }
        }

        // epilogue: cg even pair (cg, cg+1)
        bool isQ = (c < 2);
        bool isV = (c >= 4);
#pragma unroll
        for (int nj = 0; nj < 4; ++nj) {
            int cg = c*64 + wn + nj*8 + 2*q;
#pragma unroll
            for (int mi = 0; mi < 2; ++mi) {
                int r = mBase + wm + mi*16 + g;
                int b = r >> 8, n = r & 255;
                float4 a4 = acc[mi][nj];
                if (!isV) {
                    int cc = isQ ? cg : (cg - 128);
                    int h = cc >> 5, d = cc & 31;
                    float s = isQ ? scale : 1.0f;
                    size_t w0 = (((size_t)b*H_ + h)*N_ + n)*(DH/2) + (d >> 1);
                    size_t w1 = (((size_t)b*H_ + h)*N_ + (n+8))*(DH/2) + (d >> 1);
                    uint32_t* dst = isQ ? g_qh : g_kh;
                    dst[w0] = pack2(a4.x*s, a4.y*s);
                    dst[w1] = pack2(a4.z*s, a4.w*s);
                } else {
                    // V transposed: word(d, n2) = {V[2n2][d], V[2n2+1][d]}
                    int cc = cg - 256;
                    int h = cc >> 5, d = cc & 31;
                    float px = __shfl_xor_sync(0xffffffffu, a4.x, 4);
                    float py = __shfl_xor_sync(0xffffffffu, a4.y, 4);
                    float pz = __shfl_xor_sync(0xffffffffu, a4.z, 4);
                    float pw = __shfl_xor_sync(0xffffffffu, a4.w, 4);
                    if ((g & 1) == 0) {   // even row of the pair
                        size_t vb = (((size_t)b*H_ + h)*DH) * (N_/2);
                        int n2a = n >> 1, n2b = (n + 8) >> 1;
                        g_vt[vb + (size_t)d    *(N_/2) + n2a] = pack2(a4.x, px);
                        g_vt[vb + (size_t)(d+1)*(N_/2) + n2a] = pack2(a4.y, py);
                        g_vt[vb + (size_t)d    *(N_/2) + n2b] = pack2(a4.z, pz);
                        g_vt[vb + (size_t)(d+1)*(N_/2) + n2b] = pack2(a4.w, pw);
                    }
                }
            }
        }
    }
}

// ---------------------------------------------------------------------------
// Projection GEMM (fp16 mma): A-frags via ldmatrix.x4. 3 CTAs/SM.
// out = att @ pw + pb (fp32).
// ---------------------------------------------------------------------------
__global__ __launch_bounds__(256, 3) void proj_gemm_tc(const float* __restrict__ pb,
                                                       float* __restrict__ out) {
    extern __shared__ uint32_t sm[];
    uint32_t* Bs = sm + 128*QA_LD;       // [64][QB_LD]
    uint32_t AsAddr = (uint32_t)__cvta_generic_to_shared(sm);
    uint32_t BsAddr = (uint32_t)__cvta_generic_to_shared(Bs);

    int tid   = threadIdx.x;
    int mBase = blockIdx.x * 128;

#pragma unroll
    for (int it = 0; it < 8; ++it) {     // A: 128 rows x 64 words
        int idx = tid + it*256;
        int r = idx >> 4, c4 = idx & 15;
        cp_async16(AsAddr + (r*QA_LD + c4*4)*4,
                   g_atth + (size_t)(mBase + r)*(C_/2) + c4*4);
    }
    CP_COMMIT();

    int warp = tid >> 5, lane = tid & 31;
    int g = lane >> 2, q = lane & 3;
    int lm = lane >> 3, lr = lane & 7;
    int wm = (warp & 3) * 32;
    int wn = (warp >> 2) * 32;

#pragma unroll 1
    for (int c = 0; c < 2; ++c) {
        __syncthreads();
#pragma unroll
        for (int it = 0; it < 4; ++it) { // B chunk: 64 k2-rows x 64 cols
            int idx = tid + it*256;
            int r = idx >> 4, c4 = idx & 15;
            cp_async16(BsAddr + (r*QB_LD + c4*4)*4, g_pwh + r*128 + c*64 + c4*4);
        }
        CP_COMMIT();
        CP_WAIT_ALL();
        __syncthreads();

        float4 acc[2][4];
#pragma unroll
        for (int mi = 0; mi < 2; ++mi)
#pragma unroll
            for (int nj = 0; nj < 4; ++nj) acc[mi][nj] = make_float4(0.f,0.f,0.f,0.f);

#pragma unroll
        for (int kc = 0; kc < 8; ++kc) {
            uint32_t a[2][4];
#pragma unroll
            for (int mi = 0; mi < 2; ++mi) {
                uint32_t addr = AsAddr +
                    (((wm + mi*16 + (lm & 1)*8 + lr)*QA_LD) + kc*8 + (lm >> 1)*4)*4;
                ldsm_x4(a[mi][0], a[mi][1], a[mi][2], a[mi][3], addr);
            }
#pragma unroll
            for (int nj = 0; nj < 4; ++nj) {
                uint32_t b0 = Bs[(kc*8+q)*QB_LD   + wn + nj*8 + g];
                uint32_t b1 = Bs[(kc*8+q+4)*QB_LD + wn + nj*8 + g];
#pragma unroll
                for (int mi = 0; mi < 2; ++mi)
                    mma_f16(acc[mi][nj], a[mi][0], a[mi][1], a[mi][2], a[mi][3], b0, b1);
            }
        }

#pragma unroll
        for (int nj = 0; nj < 4; ++nj) {
            int cg = c*64 + wn + nj*8 + 2*q;
            float2 bias = *(const float2*)(pb + cg);
#pragma unroll
            for (int mi = 0; mi < 2; ++mi) {
                int r = mBase + wm + mi*16 + g;
                float2 v0 = make_float2(acc[mi][nj].x + bias.x, acc[mi][nj].y + bias.y);
                float2 v1 = make_float2(acc[mi][nj].z + bias.x, acc[mi][nj].w + bias.y);
                *(float2*)&out[(size_t)r*C_ + cg]     = v0;
                *(float2*)&out[(size_t)(r+8)*C_ + cg] = v1;
            }
        }
    }
}

// ---------------------------------------------------------------------------
// Attention (fp16 mma): block per (b, h, half), 3 CTAs/SM (3 chunks of 64
// keys, 8 live S-frags). K and V fragments loaded via ldmatrix.x4 (one LDSM
// serves 2 mma steps). QK C-frags feed PV A-frags by fp16x2 packing.
// ---------------------------------------------------------------------------
#define KS_LD 20    // 16 words + 4 pad (20%32=20 -> LDSM rows conflict-free)
#define VS_LD 132   // 128 words + 4 pad (132%32=4 -> conflict-free)
#define ATTN_SMEM_WORDS (256*KS_LD + 32*VS_LD)   // 9344 -> 37,376 B

__global__ __launch_bounds__(256, 3) void attn_tc() {
    extern __shared__ uint32_t sm[];
    uint32_t KsAddr = (uint32_t)__cvta_generic_to_shared(sm);
    uint32_t VsAddr = KsAddr + 256*KS_LD*4;

    int tid = threadIdx.x;
    int bid = blockIdx.x;
    int hb = bid & 1;
    int h  = (bid >> 1) & 3;
    int b  = bid >> 3;
    size_t base16 = (((size_t)b*H_ + h) * N_) * (DH/2);
    size_t baseV  = (((size_t)b*H_ + h) * DH) * (N_/2);

#pragma unroll
    for (int it = 0; it < 4; ++it) {     // K: 256 keys x 16 words
        int idx = tid + it*256;
        int r = idx >> 2, c4 = idx & 3;
        cp_async16(KsAddr + (r*KS_LD + c4*4)*4, g_kh + base16 + (size_t)r*16 + c4*4);
    }
#pragma unroll
    for (int it = 0; it < 4; ++it) {     // V: 32 dims x 128 words
        int idx = tid + it*256;
        int d = idx >> 5, c32 = idx & 31;
        cp_async16(VsAddr + (d*VS_LD + c32*4)*4, g_vt + baseV + (size_t)d*(N_/2) + c32*4);
    }
    CP_COMMIT();

    int warp = tid >> 5, lane = tid & 31;
    int g = lane >> 2, q = lane & 3;
    int lm = lane >> 3, lr = lane & 7;   // ldmatrix: matrix id, row id
    int rloc = warp * 16;                // 0..112 within half
    int i = hb*2 + (warp >> 2);          // slice
    int r0g = hb*128 + rloc + g;         // global query rows
    int r1g = r0g + 8;

    // Q A-frags: direct LDG of pre-scaled packed words (overlaps K/V copies)
    uint32_t qa[2][4];
    {
        const uint32_t* qp0 = g_qh + base16 + (size_t)r0g*16;
        const uint32_t* qp1 = g_qh + base16 + (size_t)r1g*16;
#pragma unroll
        for (int kc = 0; kc < 2; ++kc) {
            qa[kc][0] = qp0[kc*8 + q];
            qa[kc][1] = qp1[kc*8 + q];
            qa[kc][2] = qp0[kc*8 + q + 4];
            qa[kc][3] = qp1[kc*8 + q + 4];
        }
    }
    CP_WAIT_ALL();
    __syncthreads();

    const float* bb = g_bias + ((size_t)((i*H_ + h)*INTV + (rloc & 63)))*KN;

    float s0r = 0.f, s1r = 0.f;
    float4 o[4];
#pragma unroll
    for (int nj = 0; nj < 4; ++nj) o[nj] = make_float4(0.f,0.f,0.f,0.f);

#pragma unroll
    for (int ch = 0; ch < 3; ++ch) {     // 3 chunks of 64 keys
        int cbase = ch * 64;

        // S frags (16 x 64), bias-initialized
        float4 c[8];
#pragma unroll
        for (int kt = 0; kt < 8; ++kt) {
            int col = cbase + kt*8 + 2*q;
            float2 b0 = *(const float2*)(bb + (size_t)(g)*KN + col);
            float2 b1 = *(const float2*)(bb + (size_t)(g+8)*KN + col);
            c[kt] = make_float4(b0.x, b0.y, b1.x, b1.y);
        }

        // S = (scaled Q) K^T + bias. K frags via LDSM.x4: one load per 2 kt.
#pragma unroll
        for (int kc = 0; kc < 2; ++kc) {
#pragma unroll
            for (int p = 0; p < 4; ++p) {
                int ktp = 2*p + (lm >> 1);
                int col = cbase + ktp*8;
                int off = (col >= i*INTV) ? INTV : 0;
                uint32_t addr = KsAddr +
                    (((col + off + lr)*KS_LD) + kc*8 + (lm & 1)*4)*4;
                uint32_t b00, b01, b10, b11;
                ldsm_x4(b00, b01, b10, b11, addr);
                mma_f16(c[2*p],   qa[kc][0], qa[kc][1], qa[kc][2], qa[kc][3], b00, b01);
                mma_f16(c[2*p+1], qa[kc][0], qa[kc][1], qa[kc][2], qa[kc][3], b10, b11);
            }
        }

        // exp (no max shift) + row sums
        float cs0 = 0.f, cs1 = 0.f;
#pragma unroll
        for (int kt = 0; kt < 8; ++kt) {
            c[kt].x = __expf(c[kt].x);
            c[kt].y = __expf(c[kt].y);
            c[kt].z = __expf(c[kt].z);
            c[kt].w = __expf(c[kt].w);
            cs0 += c[kt].x + c[kt].y;
            cs1 += c[kt].z + c[kt].w;
        }
        cs0 += __shfl_xor_sync(0xffffffffu, cs0, 1);
        cs0 += __shfl_xor_sync(0xffffffffu, cs0, 2);
        cs1 += __shfl_xor_sync(0xffffffffu, cs1, 1);
        cs1 += __shfl_xor_sync(0xffffffffu, cs1, 2);
        s0r += cs0;
        s1r += cs1;

        // PV: C-frag -> fp16 A-frag by packing; V frags via LDSM.x4
        // (one load per 2 nj).
#pragma unroll
        for (int kp = 0; kp < 4; ++kp) {
            uint32_t a0 = pack2(c[2*kp].x,   c[2*kp].y);
            uint32_t a1 = pack2(c[2*kp].z,   c[2*kp].w);
            uint32_t a2 = pack2(c[2*kp+1].x, c[2*kp+1].y);
            uint32_t a3 = pack2(c[2*kp+1].z, c[2*kp+1].w);
            int col = cbase + kp*16;
            int off = (col >= i*INTV) ? INTV : 0;
            int kb2 = (col + off) >> 1;
#pragma unroll
            for (int pj = 0; pj < 2; ++pj) {
                int njp = pj*2 + (lm >> 1);
                uint32_t addr = VsAddr +
                    (((njp*8 + lr)*VS_LD) + kb2 + (lm & 1)*4)*4;
                uint32_t v00, v01, v10, v11;
                ldsm_x4(v00, v01, v10, v11, addr);
                mma_f16(o[pj*2],   a0, a1, a2, a3, v00, v01);
                mma_f16(o[pj*2+1], a0, a1, a2, a3, v10, v11);
            }
        }
    }

    float inv0 = 1.f / s0r;
    float inv1 = 1.f / s1r;

    // normalize + pack fp16x2 + write (warp-exclusive rows)
#pragma unroll
    for (int nj = 0; nj < 4; ++nj) {
        int d2 = h*(DH/2) + nj*4 + q;   // word index of col pair (2q,2q+1)
        g_atth[((size_t)b*N_ + r0g)*(C_/2) + d2] = pack2(o[nj].x*inv0, o[nj].y*inv0);
        g_atth[((size_t)b*N_ + r1g)*(C_/2) + d2] = pack2(o[nj].z*inv1, o[nj].w*inv1);
    }
}

// ---------------------------------------------------------------------------
// Launch
// ---------------------------------------------------------------------------
extern "C" void kernel_launch(void* const* d_in, const int* in_sizes, int n_in,
                              void* d_out, int out_size) {
    const float* x      = (const float*)d_in[0];
    const float* q_w    = (const float*)d_in[1];
    const float* kv_w   = (const float*)d_in[2];
    const float* proj_w = (const float*)d_in[3];
    const float* proj_b = (const float*)d_in[4];
    const float* rpb    = (const float*)d_in[5];
    const int*   rel    = (const int*)d_in[6];
    float* out = (float*)d_out;

    const int gemm_smem = QKV_SMEM_WORDS * 4;    // 53,248 B -> 3 CTAs/SM
    const int attn_smem = ATTN_SMEM_WORDS * 4;   // 37,376 B -> 3 CTAs/SM
    cudaFuncSetAttribute(qkv_gemm_tc,  cudaFuncAttributeMaxDynamicSharedMemorySize, gemm_smem);
    cudaFuncSetAttribute(proj_gemm_tc, cudaFuncAttributeMaxDynamicSharedMemorySize, gemm_smem);
    cudaFuncSetAttribute(attn_tc,      cudaFuncAttributeMaxDynamicSharedMemorySize, attn_smem);

    bias_kernel<<<(T_*H_*INTV*KN + 255)/256, 256>>>(rpb, rel);
    wcvt_kernel<<<(64*384 + 64*128 + 255)/256, 256>>>(q_w, kv_w, proj_w);
    qkv_gemm_tc<<<(B_*N_)/128, 256, gemm_smem>>>(x);
    attn_tc<<<B_*H_*2, 256, attn_smem>>>();
    proj_gemm_tc<<<(B_*N_)/128, 256, gemm_smem>>>(proj_b, out);
}

// round 17
// speedup vs baseline: 1.2263x; 1.1225x over previous
#include <cuda_runtime.h>
#include <cuda_fp16.h>
#include <cstdint>

// Problem constants
#define B_   1024
#define N_   256
#define C_   128
#define H_   4
#define T_   4
#define DH   32
#define INTV 64
#define KN   192   // keys per slice = N - INTV

// Scratch (device globals). q/k/att packed fp16x2 along contraction dim;
// v TRANSPOSED ([d][key]) packed along keys. Layouts match ldmatrix.m8n8.
__device__ uint32_t g_qh[(size_t)B_*H_*N_*(DH/2)];   // [b][h][n][d2], pre-scaled
__device__ uint32_t g_kh[(size_t)B_*H_*N_*(DH/2)];   // [b][h][n][d2]
__device__ uint32_t g_vt[(size_t)B_*H_*DH*(N_/2)];   // [b][h][d][n2]
__device__ uint32_t g_atth[(size_t)B_*N_*(C_/2)];    // [b*n][c2]
// bias packed fp16 in C-fragment order: [i][h][grp 0..3][g 0..7][kk2 0..95]
// uint2 = {pack(row grp*16+g, cols 2kk2,2kk2+1), pack(row grp*16+g+8, same)}
__device__ uint2    g_bias2[T_*H_*4*8*(KN/2)];
__device__ uint32_t g_wqkv[64*384];                  // word(k2,c); q_w pre-scaled
__device__ uint32_t g_pwh[64*128];                   // word(k2,c)

// ---------------------------------------------------------------------------
// helpers
// ---------------------------------------------------------------------------
__device__ __forceinline__ uint32_t pack2(float lo, float hi) {
    uint32_t u;
    asm("cvt.rn.f16x2.f32 %0, %1, %2;" : "=r"(u) : "f"(hi), "f"(lo));
    return u;
}

__device__ __forceinline__ void mma_f16(float4& d,
                                        uint32_t a0, uint32_t a1, uint32_t a2, uint32_t a3,
                                        uint32_t b0, uint32_t b1) {
    asm volatile(
        "mma.sync.aligned.m16n8k16.row.col.f32.f16.f16.f32 "
        "{%0,%1,%2,%3}, {%4,%5,%6,%7}, {%8,%9}, {%0,%1,%2,%3};"
        : "+f"(d.x), "+f"(d.y), "+f"(d.z), "+f"(d.w)
        : "r"(a0), "r"(a1), "r"(a2), "r"(a3), "r"(b0), "r"(b1));
}

__device__ __forceinline__ void ldsm_x4(uint32_t& r0, uint32_t& r1,
                                        uint32_t& r2, uint32_t& r3, uint32_t addr) {
    asm volatile("ldmatrix.sync.aligned.m8n8.x4.shared.b16 {%0,%1,%2,%3}, [%4];"
                 : "=r"(r0), "=r"(r1), "=r"(r2), "=r"(r3) : "r"(addr));
}

__device__ __forceinline__ void cp_async16(uint32_t smem_addr, const void* gptr) {
    asm volatile("cp.async.cg.shared.global [%0], [%1], 16;"
                 :: "r"(smem_addr), "l"(gptr));
}
#define CP_COMMIT()   asm volatile("cp.async.commit_group;" ::: "memory")
#define CP_WAIT_ALL() asm volatile("cp.async.wait_group 0;" ::: "memory")

// ---------------------------------------------------------------------------
// Bias precompute: fp16x2 fragment-ordered pairs
// ---------------------------------------------------------------------------
__global__ void bias_kernel(const float* __restrict__ rpb,
                            const int* __restrict__ rel) {
    int idx = blockIdx.x * 256 + threadIdx.x;
    if (idx >= T_*H_*4*8*(KN/2)) return;
    int kk2 = idx % (KN/2);
    int g   = (idx / (KN/2)) % 8;
    int grp = (idx / (KN/2*8)) % 4;
    int h   = (idx / (KN/2*8*4)) % H_;
    int i   =  idx / (KN/2*8*4*H_);
    int r0 = grp*16 + g, r1 = r0 + 8;
    int qg0 = i*INTV + r0, qg1 = i*INTV + r1;
    int kk0 = 2*kk2, kk1 = 2*kk2 + 1;
    int kg0 = (kk0 < i*INTV) ? kk0 : kk0 + INTV;
    int kg1 = (kk1 < i*INTV) ? kk1 : kk1 + INTV;
    float v00 = rpb[rel[qg0*N_ + kg0]*H_ + h];
    float v01 = rpb[rel[qg0*N_ + kg1]*H_ + h];
    float v10 = rpb[rel[qg1*N_ + kg0]*H_ + h];
    float v11 = rpb[rel[qg1*N_ + kg1]*H_ + h];
    g_bias2[idx] = make_uint2(pack2(v00, v01), pack2(v10, v11));
}

// ---------------------------------------------------------------------------
// Weight pre-pack to fp16x2 (one shot): pairs along k; q_w pre-scaled.
// ---------------------------------------------------------------------------
__global__ void wcvt_kernel(const float* __restrict__ qw,
                            const float* __restrict__ kvw,
                            const float* __restrict__ pw) {
    const float scale = 0.17677669529663687f;  // 32^-0.5
    int idx = blockIdx.x * 256 + threadIdx.x;
    if (idx < 64*384) {
        int k2 = idx / 384, c = idx % 384;
        float lo, hi;
        if (c < 128) {
            lo = qw[(2*k2)*128 + c]   * scale;
            hi = qw[(2*k2+1)*128 + c] * scale;
        } else {
            lo = kvw[(2*k2)*256 + (c-128)];
            hi = kvw[(2*k2+1)*256 + (c-128)];
        }
        g_wqkv[idx] = pack2(lo, hi);
    } else {
        int p = idx - 64*384;
        if (p < 64*128) {
            int k2 = p / 128, c = p % 128;
            g_pwh[p] = pack2(pw[(2*k2)*128 + c], pw[(2*k2+1)*128 + c]);
        }
    }
}

// ---------------------------------------------------------------------------
// QKV GEMM (fp16 mma): 256 threads, 128-row M-tile, 6 N-chunks of 64.
// A-frags via ldmatrix.x4. smem 53.2 KB, regs<=85 -> 3 CTAs/SM.
// ---------------------------------------------------------------------------
#define QA_LD 68
#define QB_LD 72
#define QKV_SMEM_WORDS (128*QA_LD + 64*QB_LD)   // 13312 -> 53,248 B

__global__ __launch_bounds__(256, 3) void qkv_gemm_tc(const float* __restrict__ x) {
    extern __shared__ uint32_t sm[];
    uint32_t* As = sm;
    uint32_t* Bs = sm + 128*QA_LD;
    uint32_t AsAddr = (uint32_t)__cvta_generic_to_shared(As);
    uint32_t BsAddr = (uint32_t)__cvta_generic_to_shared(Bs);

    int tid   = threadIdx.x;
    int mBase = blockIdx.x * 128;

#pragma unroll
    for (int it = 0; it < 16; ++it) {    // A: 128x128 fp32 -> fp16x2
        int idx = tid + it*256;
        int r = idx >> 5, c4 = idx & 31;
        float4 v = *(const float4*)(x + (size_t)(mBase + r)*128 + c4*4);
        uint2 w = make_uint2(pack2(v.x, v.y), pack2(v.z, v.w));
        *(uint2*)&As[r*QA_LD + c4*2] = w;
    }

    int warp = tid >> 5, lane = tid & 31;
    int g = lane >> 2, q = lane & 3;
    int lm = lane >> 3, lr = lane & 7;
    int wm = (warp & 3) * 32;
    int wn = (warp >> 2) * 32;

#pragma unroll 1
    for (int c = 0; c < 6; ++c) {
        __syncthreads();
#pragma unroll
        for (int it = 0; it < 4; ++it) { // B chunk: 64 k2-rows x 64 cols
            int idx = tid + it*256;
            int r = idx >> 4, c4 = idx & 15;
            cp_async16(BsAddr + (r*QB_LD + c4*4)*4, g_wqkv + r*384 + c*64 + c4*4);
        }
        CP_COMMIT();
        CP_WAIT_ALL();
        __syncthreads();

        float4 acc[2][4];
#pragma unroll
        for (int mi = 0; mi < 2; ++mi)
#pragma unroll
            for (int nj = 0; nj < 4; ++nj) acc[mi][nj] = make_float4(0.f,0.f,0.f,0.f);

#pragma unroll
        for (int kc = 0; kc < 8; ++kc) {
            uint32_t a[2][4];
#pragma unroll
            for (int mi = 0; mi < 2; ++mi) {
                uint32_t addr = AsAddr +
                    (((wm + mi*16 + (lm & 1)*8 + lr)*QA_LD) + kc*8 + (lm >> 1)*4)*4;
                ldsm_x4(a[mi][0], a[mi][1], a[mi][2], a[mi][3], addr);
            }
#pragma unroll
            for (int nj = 0; nj < 4; ++nj) {
                uint32_t b0 = Bs[(kc*8+q)*QB_LD   + wn + nj*8 + g];
                uint32_t b1 = Bs[(kc*8+q+4)*QB_LD + wn + nj*8 + g];
#pragma unroll
                for (int mi = 0; mi < 2; ++mi)
                    mma_f16(acc[mi][nj], a[mi][0], a[mi][1], a[mi][2], a[mi][3], b0, b1);
            }
        }

        bool isQ = (c < 2);
        bool isV = (c >= 4);
#pragma unroll
        for (int nj = 0; nj < 4; ++nj) {
            int cg = c*64 + wn + nj*8 + 2*q;
#pragma unroll
            for (int mi = 0; mi < 2; ++mi) {
                int r = mBase + wm + mi*16 + g;
                int b = r >> 8, n = r & 255;
                float4 a4 = acc[mi][nj];
                if (!isV) {
                    int cc = isQ ? cg : (cg - 128);
                    int h = cc >> 5, d = cc & 31;
                    size_t w0 = (((size_t)b*H_ + h)*N_ + n)*(DH/2) + (d >> 1);
                    size_t w1 = (((size_t)b*H_ + h)*N_ + (n+8))*(DH/2) + (d >> 1);
                    uint32_t* dst = isQ ? g_qh : g_kh;
                    dst[w0] = pack2(a4.x, a4.y);
                    dst[w1] = pack2(a4.z, a4.w);
                } else {
                    int cc = cg - 256;
                    int h = cc >> 5, d = cc & 31;
                    float px = __shfl_xor_sync(0xffffffffu, a4.x, 4);
                    float py = __shfl_xor_sync(0xffffffffu, a4.y, 4);
                    float pz = __shfl_xor_sync(0xffffffffu, a4.z, 4);
                    float pw = __shfl_xor_sync(0xffffffffu, a4.w, 4);
                    if ((g & 1) == 0) {
                        size_t vb = (((size_t)b*H_ + h)*DH) * (N_/2);
                        int n2a = n >> 1, n2b = (n + 8) >> 1;
                        g_vt[vb + (size_t)d    *(N_/2) + n2a] = pack2(a4.x, px);
                        g_vt[vb + (size_t)(d+1)*(N_/2) + n2a] = pack2(a4.y, py);
                        g_vt[vb + (size_t)d    *(N_/2) + n2b] = pack2(a4.z, pz);
                        g_vt[vb + (size_t)(d+1)*(N_/2) + n2b] = pack2(a4.w, pw);
                    }
                }
            }
        }
    }
}

// ---------------------------------------------------------------------------
// Projection GEMM (fp16 mma): A-frags via ldmatrix.x4. 3 CTAs/SM.
// ---------------------------------------------------------------------------
__global__ __launch_bounds__(256, 3) void proj_gemm_tc(const float* __restrict__ pb,
                                                       float* __restrict__ out) {
    extern __shared__ uint32_t sm[];
    uint32_t* Bs = sm + 128*QA_LD;
    uint32_t AsAddr = (uint32_t)__cvta_generic_to_shared(sm);
    uint32_t BsAddr = (uint32_t)__cvta_generic_to_shared(Bs);

    int tid   = threadIdx.x;
    int mBase = blockIdx.x * 128;

#pragma unroll
    for (int it = 0; it < 8; ++it) {
        int idx = tid + it*256;
        int r = idx >> 4, c4 = idx & 15;
        cp_async16(AsAddr + (r*QA_LD + c4*4)*4,
                   g_atth + (size_t)(mBase + r)*(C_/2) + c4*4);
    }
    CP_COMMIT();

    int warp = tid >> 5, lane = tid & 31;
    int g = lane >> 2, q = lane & 3;
    int lm = lane >> 3, lr = lane & 7;
    int wm = (warp & 3) * 32;
    int wn = (warp >> 2) * 32;

#pragma unroll 1
    for (int c = 0; c < 2; ++c) {
        __syncthreads();
#pragma unroll
        for (int it = 0; it < 4; ++it) {
            int idx = tid + it*256;
            int r = idx >> 4, c4 = idx & 15;
            cp_async16(BsAddr + (r*QB_LD + c4*4)*4, g_pwh + r*128 + c*64 + c4*4);
        }
        CP_COMMIT();
        CP_WAIT_ALL();
        __syncthreads();

        float4 acc[2][4];
#pragma unroll
        for (int mi = 0; mi < 2; ++mi)
#pragma unroll
            for (int nj = 0; nj < 4; ++nj) acc[mi][nj] = make_float4(0.f,0.f,0.f,0.f);

#pragma unroll
        for (int kc = 0; kc < 8; ++kc) {
            uint32_t a[2][4];
#pragma unroll
            for (int mi = 0; mi < 2; ++mi) {
                uint32_t addr = AsAddr +
                    (((wm + mi*16 + (lm & 1)*8 + lr)*QA_LD) + kc*8 + (lm >> 1)*4)*4;
                ldsm_x4(a[mi][0], a[mi][1], a[mi][2], a[mi][3], addr);
            }
#pragma unroll
            for (int nj = 0; nj < 4; ++nj) {
                uint32_t b0 = Bs[(kc*8+q)*QB_LD   + wn + nj*8 + g];
                uint32_t b1 = Bs[(kc*8+q+4)*QB_LD + wn + nj*8 + g];
#pragma unroll
                for (int mi = 0; mi < 2; ++mi)
                    mma_f16(acc[mi][nj], a[mi][0], a[mi][1], a[mi][2], a[mi][3], b0, b1);
            }
        }

#pragma unroll
        for (int nj = 0; nj < 4; ++nj) {
            int cg = c*64 + wn + nj*8 + 2*q;
            float2 bias = *(const float2*)(pb + cg);
#pragma unroll
            for (int mi = 0; mi < 2; ++mi) {
                int r = mBase + wm + mi*16 + g;
                float2 v0 = make_float2(acc[mi][nj].x + bias.x, acc[mi][nj].y + bias.y);
                float2 v1 = make_float2(acc[mi][nj].z + bias.x, acc[mi][nj].w + bias.y);
                *(float2*)&out[(size_t)r*C_ + cg]     = v0;
                *(float2*)&out[(size_t)(r+8)*C_ + cg] = v1;
            }
        }
    }
}

// ---------------------------------------------------------------------------
// Attention (fp16 mma): block per (b, h, half), 3 CTAs/SM, 3 chunks of 64
// keys. K/V frags via ldmatrix.x4; bias via ONE LDG.64 per fragment (fp16
// fragment-ordered). QK C-frags feed PV A-frags by fp16x2 packing.
// ---------------------------------------------------------------------------
#define KS_LD 20
#define VS_LD 132
#define ATTN_SMEM_WORDS (256*KS_LD + 32*VS_LD)   // 9344 -> 37,376 B

__global__ __launch_bounds__(256, 3) void attn_tc() {
    extern __shared__ uint32_t sm[];
    uint32_t KsAddr = (uint32_t)__cvta_generic_to_shared(sm);
    uint32_t VsAddr = KsAddr + 256*KS_LD*4;

    int tid = threadIdx.x;
    int bid = blockIdx.x;
    int hb = bid & 1;
    int h  = (bid >> 1) & 3;
    int b  = bid >> 3;
    size_t base16 = (((size_t)b*H_ + h) * N_) * (DH/2);
    size_t baseV  = (((size_t)b*H_ + h) * DH) * (N_/2);

#pragma unroll
    for (int it = 0; it < 4; ++it) {
        int idx = tid + it*256;
        int r = idx >> 2, c4 = idx & 3;
        cp_async16(KsAddr + (r*KS_LD + c4*4)*4, g_kh + base16 + (size_t)r*16 + c4*4);
    }
#pragma unroll
    for (int it = 0; it < 4; ++it) {
        int idx = tid + it*256;
        int d = idx >> 5, c32 = idx & 31;
        cp_async16(VsAddr + (d*VS_LD + c32*4)*4, g_vt + baseV + (size_t)d*(N_/2) + c32*4);
    }
    CP_COMMIT();

    int warp = tid >> 5, lane = tid & 31;
    int g = lane >> 2, q = lane & 3;
    int lm = lane >> 3, lr = lane & 7;
    int rloc = warp * 16;
    int i = hb*2 + (warp >> 2);
    int r0g = hb*128 + rloc + g;
    int r1g = r0g + 8;

    // Q A-frags: direct LDG (overlaps K/V copies)
    uint32_t qa[2][4];
    {
        const uint32_t* qp0 = g_qh + base16 + (size_t)r0g*16;
        const uint32_t* qp1 = g_qh + base16 + (size_t)r1g*16;
#pragma unroll
        for (int kc = 0; kc < 2; ++kc) {
            qa[kc][0] = qp0[kc*8 + q];
            qa[kc][1] = qp1[kc*8 + q];
            qa[kc][2] = qp0[kc*8 + q + 4];
            qa[kc][3] = qp1[kc*8 + q + 4];
        }
    }
    CP_WAIT_ALL();
    __syncthreads();

    // fragment-ordered fp16 bias: [i][h][grp=warp&3][g][kk2]
    const uint2* bb2 = g_bias2 +
        ((((size_t)i*H_ + h)*4 + (warp & 3))*8 + g)*(KN/2);

    float s0r = 0.f, s1r = 0.f;
    float4 o[4];
#pragma unroll
    for (int nj = 0; nj < 4; ++nj) o[nj] = make_float4(0.f,0.f,0.f,0.f);

#pragma unroll
    for (int ch = 0; ch < 3; ++ch) {
        int cbase = ch * 64;

        // S frags (16 x 64), bias-initialized: one LDG.64 per fragment
        float4 c[8];
#pragma unroll
        for (int kt = 0; kt < 8; ++kt) {
            uint2 w = bb2[cbase/2 + kt*4 + q];
            float2 f0 = __half22float2(*(__half2*)&w.x);
            float2 f1 = __half22float2(*(__half2*)&w.y);
            c[kt] = make_float4(f0.x, f0.y, f1.x, f1.y);
        }

        // S = (scaled Q) K^T + bias. K frags via LDSM.x4.
#pragma unroll
        for (int kc = 0; kc < 2; ++kc) {
#pragma unroll
            for (int p = 0; p < 4; ++p) {
                int ktp = 2*p + (lm >> 1);
                int col = cbase + ktp*8;
                int off = (col >= i*INTV) ? INTV : 0;
                uint32_t addr = KsAddr +
                    (((col + off + lr)*KS_LD) + kc*8 + (lm & 1)*4)*4;
                uint32_t b00, b01, b10, b11;
                ldsm_x4(b00, b01, b10, b11, addr);
                mma_f16(c[2*p],   qa[kc][0], qa[kc][1], qa[kc][2], qa[kc][3], b00, b01);
                mma_f16(c[2*p+1], qa[kc][0], qa[kc][1], qa[kc][2], qa[kc][3], b10, b11);
            }
        }

        // exp (no max shift) + row sums
        float cs0 = 0.f, cs1 = 0.f;
#pragma unroll
        for (int kt = 0; kt < 8; ++kt) {
            c[kt].x = __expf(c[kt].x);
            c[kt].y = __expf(c[kt].y);
            c[kt].z = __expf(c[kt].z);
            c[kt].w = __expf(c[kt].w);
            cs0 += c[kt].x + c[kt].y;
            cs1 += c[kt].z + c[kt].w;
        }
        cs0 += __shfl_xor_sync(0xffffffffu, cs0, 1);
        cs0 += __shfl_xor_sync(0xffffffffu, cs0, 2);
        cs1 += __shfl_xor_sync(0xffffffffu, cs1, 1);
        cs1 += __shfl_xor_sync(0xffffffffu, cs1, 2);
        s0r += cs0;
        s1r += cs1;

        // PV: C-frag -> fp16 A-frag by packing; V frags via LDSM.x4
#pragma unroll
        for (int kp = 0; kp < 4; ++kp) {
            uint32_t a0 = pack2(c[2*kp].x,   c[2*kp].y);
            uint32_t a1 = pack2(c[2*kp].z,   c[2*kp].w);
            uint32_t a2 = pack2(c[2*kp+1].x, c[2*kp+1].y);
            uint32_t a3 = pack2(c[2*kp+1].z, c[2*kp+1].w);
            int col = cbase + kp*16;
            int off = (col >= i*INTV) ? INTV : 0;
            int kb2 = (col + off) >> 1;
#pragma unroll
            for (int pj = 0; pj < 2; ++pj) {
                int njp = pj*2 + (lm >> 1);
                uint32_t addr = VsAddr +
                    (((njp*8 + lr)*VS_LD) + kb2 + (lm & 1)*4)*4;
                uint32_t v00, v01, v10, v11;
                ldsm_x4(v00, v01, v10, v11, addr);
                mma_f16(o[pj*2],   a0, a1, a2, a3, v00, v01);
                mma_f16(o[pj*2+1], a0, a1, a2, a3, v10, v11);
            }
        }
    }

    float inv0 = 1.f / s0r;
    float inv1 = 1.f / s1r;

#pragma unroll
    for (int nj = 0; nj < 4; ++nj) {
        int d2 = h*(DH/2) + nj*4 + q;
        g_atth[((size_t)b*N_ + r0g)*(C_/2) + d2] = pack2(o[nj].x*inv0, o[nj].y*inv0);
        g_atth[((size_t)b*N_ + r1g)*(C_/2) + d2] = pack2(o[nj].z*inv1, o[nj].w*inv1);
    }
}

// ---------------------------------------------------------------------------
// Launch
// ---------------------------------------------------------------------------
extern "C" void kernel_launch(void* const* d_in, const int* in_sizes, int n_in,
                              void* d_out, int out_size) {
    const float* x      = (const float*)d_in[0];
    const float* q_w    = (const float*)d_in[1];
    const float* kv_w   = (const float*)d_in[2];
    const float* proj_w = (const float*)d_in[3];
    const float* proj_b = (const float*)d_in[4];
    const float* rpb    = (const float*)d_in[5];
    const int*   rel    = (const int*)d_in[6];
    float* out = (float*)d_out;

    const int gemm_smem = QKV_SMEM_WORDS * 4;    // 53,248 B -> 3 CTAs/SM
    const int attn_smem = ATTN_SMEM_WORDS * 4;   // 37,376 B -> 3 CTAs/SM
    cudaFuncSetAttribute(qkv_gemm_tc,  cudaFuncAttributeMaxDynamicSharedMemorySize, gemm_smem);
    cudaFuncSetAttribute(proj_gemm_tc, cudaFuncAttributeMaxDynamicSharedMemorySize, gemm_smem);
    cudaFuncSetAttribute(attn_tc,      cudaFuncAttributeMaxDynamicSharedMemorySize, attn_smem);

    bias_kernel<<<(T_*H_*4*8*(KN/2) + 255)/256, 256>>>(rpb, rel);
    wcvt_kernel<<<(64*384 + 64*128 + 255)/256, 256>>>(q_w, kv_w, proj_w);
    qkv_gemm_tc<<<(B_*N_)/128, 256, gemm_smem>>>(x);
    attn_tc<<<B_*H_*2, 256, attn_smem>>>();
    proj_gemm_tc<<<(B_*N_)/128, 256, gemm_smem>>>(proj_b, out);
}